// round 1
// baseline (speedup 1.0000x reference)
#include <cuda_runtime.h>
#include <math.h>

#define Bb 64
#define Cc 8
#define Nn 2048
#define Tt 64
#define NT4 (Nn * Tt / 4)   // 32768 float4 per (b, channel)

// scratch (no allocations allowed)
__device__ float g_k[Bb * Cc * Tt];      // 32768 floats
__device__ float g_att[Bb * Cc * Cc];    // 4096 floats

// ---------------------------------------------------------------------------
// Kernel 1: k[b,c,t] = sum_n x[b,c,n,t] * alpha[n]
// one block per (b,c); 256 threads = 16 rows x 16 float4 lanes
// ---------------------------------------------------------------------------
__global__ void k_reduce(const float* __restrict__ x,
                         const float* __restrict__ alpha) {
    int bc = blockIdx.x;                       // 0..511
    const float* xp = x + (long)bc * Nn * Tt;

    __shared__ float s_alpha[Nn];              // 8 KB
    for (int i = threadIdx.x; i < Nn; i += blockDim.x) s_alpha[i] = alpha[i];
    __syncthreads();

    int t4  = threadIdx.x & 15;                // float4 lane within T
    int row = threadIdx.x >> 4;                // 0..15

    float4 acc = make_float4(0.f, 0.f, 0.f, 0.f);
    #pragma unroll 4
    for (int n = row; n < Nn; n += 16) {
        float4 v = reinterpret_cast<const float4*>(xp + n * Tt)[t4];
        float a = s_alpha[n];
        acc.x += v.x * a; acc.y += v.y * a;
        acc.z += v.z * a; acc.w += v.w * a;
    }

    __shared__ float4 s_red[256];              // 4 KB
    s_red[threadIdx.x] = acc;
    __syncthreads();
    #pragma unroll
    for (int off = 8; off >= 1; off >>= 1) {
        if (row < off) {
            float4 o = s_red[(row + off) * 16 + t4];
            acc.x += o.x; acc.y += o.y; acc.z += o.z; acc.w += o.w;
            s_red[threadIdx.x] = acc;
        }
        __syncthreads();
    }
    if (row == 0)
        reinterpret_cast<float4*>(g_k + bc * Tt)[t4] = acc;
}

// ---------------------------------------------------------------------------
// Kernel 2: scores[b,c,d] = k[b,c,:] @ Wc @ k[b,d,:] ; att = softmax_d
// one block per b, 64 threads
// ---------------------------------------------------------------------------
__global__ void k_att(const float* __restrict__ Wc) {
    int b = blockIdx.x;
    int tid = threadIdx.x;                     // 0..63

    __shared__ float sW[64][64];               // 16 KB
    __shared__ float sk[8][64];
    __shared__ float sm[8][64];
    __shared__ float ssc[8][8];

    for (int i = tid; i < 64 * 64; i += 64) sW[i >> 6][i & 63] = Wc[i];
    for (int i = tid; i < 8 * 64; i += 64)  sk[i >> 6][i & 63] = g_k[b * Cc * Tt + i];
    __syncthreads();

    // m[c][s] = sum_t k[c][t] * Wc[t][s], thread handles column s = tid
    #pragma unroll
    for (int c = 0; c < 8; c++) {
        float acc = 0.f;
        #pragma unroll
        for (int t = 0; t < 64; t++) acc += sk[c][t] * sW[t][tid];
        sm[c][tid] = acc;
    }
    __syncthreads();

    // scores[c][d] = sum_s m[c][s] * k[d][s] : 64 (c,d) pairs, one per thread
    int c = tid >> 3, d = tid & 7;
    float sc = 0.f;
    #pragma unroll
    for (int s = 0; s < 64; s++) sc += sm[c][s] * sk[d][s];
    ssc[c][d] = sc;
    __syncthreads();

    // softmax over d (8 values), one thread per row c
    if (tid < 8) {
        float mx = -1e30f;
        #pragma unroll
        for (int j = 0; j < 8; j++) mx = fmaxf(mx, ssc[tid][j]);
        float e[8], sum = 0.f;
        #pragma unroll
        for (int j = 0; j < 8; j++) { e[j] = __expf(ssc[tid][j] - mx); sum += e[j]; }
        float inv = 1.f / sum;
        #pragma unroll
        for (int j = 0; j < 8; j++)
            g_att[b * Cc * Cc + tid * Cc + j] = e[j] * inv;
    }
}

// ---------------------------------------------------------------------------
// Kernel 3: out[b,c,n,t] = sum_i att[b,c,i] * x[b,i,n,t]
// 128 blocks per b x 256 threads; each thread: 1 float4 per input channel ->
// accumulates all 8 output channels
// ---------------------------------------------------------------------------
__global__ void k_agg(const float* __restrict__ x, float* __restrict__ out) {
    int b = blockIdx.x >> 7;                   // 128 blocks per batch
    int chunk = blockIdx.x & 127;

    __shared__ float sa[8][8];
    if (threadIdx.x < 64)
        sa[threadIdx.x >> 3][threadIdx.x & 7] = g_att[b * 64 + threadIdx.x];
    __syncthreads();

    int p = chunk * 256 + threadIdx.x;         // float4 index within [N*T/4]
    const float4* xb = reinterpret_cast<const float4*>(x + (long)b * Cc * Nn * Tt);
    float4* ob = reinterpret_cast<float4*>(out + (long)b * Cc * Nn * Tt);

    float4 acc[8];
    #pragma unroll
    for (int c = 0; c < 8; c++) acc[c] = make_float4(0.f, 0.f, 0.f, 0.f);

    #pragma unroll
    for (int i = 0; i < 8; i++) {
        float4 v = xb[(long)i * NT4 + p];
        #pragma unroll
        for (int c = 0; c < 8; c++) {
            float a = sa[c][i];
            acc[c].x += a * v.x; acc[c].y += a * v.y;
            acc[c].z += a * v.z; acc[c].w += a * v.w;
        }
    }
    #pragma unroll
    for (int c = 0; c < 8; c++)
        ob[(long)c * NT4 + p] = acc[c];
}

// ---------------------------------------------------------------------------
extern "C" void kernel_launch(void* const* d_in, const int* in_sizes, int n_in,
                              void* d_out, int out_size) {
    const float* x     = (const float*)d_in[0];
    const float* Wc    = (const float*)d_in[1];
    const float* alpha = (const float*)d_in[2];
    float* out = (float*)d_out;

    k_reduce<<<Bb * Cc, 256>>>(x, alpha);
    k_att<<<Bb, 64>>>(Wc);
    k_agg<<<Bb * 128, 256>>>(x, out);
}